// round 11
// baseline (speedup 1.0000x reference)
#include <cuda_runtime.h>
#include <math.h>

typedef unsigned long long ull;
typedef unsigned int uint;

#define TT 8192
#define HH 512

// ---------------- scratch: packed {flag(hi32), h_bits(lo32)} mailboxes ----------------
__device__ __align__(256) ull g_p1[(TT + 1) * HH];
__device__ __align__(256) ull g_p2[(TT + 1) * HH];

// ---------------- primitives ----------------
__device__ __forceinline__ ulonglong2 ld_rlx2(const ull* p) {
    ulonglong2 v;
    asm volatile("ld.relaxed.gpu.global.v2.u64 {%0,%1}, [%2];"
                 : "=l"(v.x), "=l"(v.y) : "l"(p) : "memory");
    return v;
}
__device__ __forceinline__ void st_rlx(ull* p, ull v) {
    asm volatile("st.relaxed.gpu.global.u64 [%0], %1;" :: "l"(p), "l"(v) : "memory");
}
__device__ __forceinline__ ull packhf(unsigned flag, float h) {
    return ((ull)flag << 32) | (ull)__float_as_uint(h);
}
__device__ __forceinline__ float lo_f(ull v) { return __uint_as_float((unsigned)v); }
__device__ __forceinline__ unsigned hi_u(ull v) { return (unsigned)(v >> 32); }

__device__ __forceinline__ void ffma2(ull& acc, ull w, ull v) {
    asm("fma.rn.f32x2 %0, %1, %2, %0;" : "+l"(acc) : "l"(w), "l"(v));
}
__device__ __forceinline__ ull packf2(float a, float b) {
    ull r;
    asm("mov.b64 %0, {%1,%2};" : "=l"(r) : "f"(a), "f"(b));
    return r;
}
__device__ __forceinline__ float2 unpack2(ull v) {
    float a, b;
    asm("mov.b64 {%0,%1}, %2;" : "=f"(a), "=f"(b) : "l"(v));
    return make_float2(a, b);
}
__device__ __forceinline__ float tanh_fast(float x) {
    float r;
    asm("tanh.approx.f32 %0, %1;" : "=f"(r) : "f"(x));
    return r;
}
__device__ __forceinline__ float sig_fast(float x) {
    return fmaf(tanh_fast(0.5f * x), 0.5f, 0.5f);
}
__device__ __forceinline__ float logsigf_(float z) {
    if (z >= 0.0f) return -log1pf(expf(-z));
    return z - log1pf(expf(z));
}

// ---------------- clear + seed ----------------
__global__ void clear_kernel(const float* __restrict__ h0) {
    size_t i = (size_t)blockIdx.x * blockDim.x + threadIdx.x;
    if (i < HH) {
        g_p1[i] = packhf(0u, h0[i]);
        g_p2[i] = packhf(0u, h0[HH + i]);
    }
    const size_t N2 = (size_t)TT * HH / 2;
    ulonglong2* a = (ulonglong2*)(g_p1 + HH);
    ulonglong2* b = (ulonglong2*)(g_p2 + HH);
    ulonglong2 z; z.x = 0ull; z.y = 0ull;
    size_t stride = (size_t)gridDim.x * blockDim.x;
    for (size_t k = i; k < N2; k += stride) { a[k] = z; b[k] = z; }
}

// ---------------- persistent pipelined LSTM ----------------
// 257 blocks x 128 threads, 2 CTAs/SM (all resident: 296 slots >= 257).
//   blocks [0,128):   layer 1 (4 outputs each)
//   blocks [128,256): layer 2 (4 outputs each)
//   block 256:        head + BCE loss
// Dot map: tt = p*8+s; p=0..15 row-pair (p<8: W_ih rows, p>=8: W_hh), s=0..7 col slice.
// Staging: threads [0,64) stage vec A (8 floats each), [64,128) stage vec B.
__global__ void __launch_bounds__(128, 2) lstm_kernel(
    const float* __restrict__ x,
    const float* __restrict__ truth,
    const float* __restrict__ c0,
    const float* __restrict__ Wih0, const float* __restrict__ Whh0,
    const float* __restrict__ bih0, const float* __restrict__ bhh0,
    const float* __restrict__ Wih1, const float* __restrict__ Whh1,
    const float* __restrict__ bih1, const float* __restrict__ bhh1,
    const float* __restrict__ Whead, const float* __restrict__ bhead,
    float* __restrict__ out)
{
    const int b  = blockIdx.x;
    const int tt = threadIdx.x;

    // ================= HEAD + LOSS =================
    if (b == 256) {
        if (tt >= 32) return;
        float w0[16], w1[16];
#pragma unroll
        for (int i = 0; i < 16; i++) {
            w0[i] = Whead[tt * 16 + i];
            w1[i] = Whead[HH + tt * 16 + i];
        }
        const float bb0 = bhead[0], bb1 = bhead[1];
        double acc = 0.0;
        const ull* pe = g_p2 + HH + tt * 16;
        for (int t = 0; t < TT; t++, pe += HH) {
            const unsigned tgt = (unsigned)(t + 1);
            ulonglong2 v[8];
            uint pend = 0xFFu;
            while (pend) {
                ulonglong2 nv[8];
#pragma unroll
                for (int i = 0; i < 8; i++)
                    if (pend & (1u << i)) nv[i] = ld_rlx2(pe + 2 * i);
#pragma unroll
                for (int i = 0; i < 8; i++)
                    if (pend & (1u << i)) {
                        if ((hi_u(nv[i].x) == tgt) & (hi_u(nv[i].y) == tgt)) {
                            v[i] = nv[i];
                            pend &= ~(1u << i);
                        }
                    }
            }
            float s0 = 0.f, s1 = 0.f;
#pragma unroll
            for (int i = 0; i < 8; i++) {
                float h0v = lo_f(v[i].x), h1v = lo_f(v[i].y);
                s0 = fmaf(w0[2 * i], h0v, s0);
                s1 = fmaf(w1[2 * i], h0v, s1);
                s0 = fmaf(w0[2 * i + 1], h1v, s0);
                s1 = fmaf(w1[2 * i + 1], h1v, s1);
            }
#pragma unroll
            for (int m = 16; m >= 1; m >>= 1) {
                s0 += __shfl_xor_sync(0xffffffffu, s0, m);
                s1 += __shfl_xor_sync(0xffffffffu, s1, m);
            }
            if (tt == 0) {
                float z0 = s0 + bb0, z1 = s1 + bb1;
                float y0 = __ldg(truth + t * 2 + 0), y1 = __ldg(truth + t * 2 + 1);
                float t0 = y0 * fmaxf(logsigf_(z0), -100.0f)
                         + (1.0f - y0) * fmaxf(logsigf_(-z0), -100.0f);
                float t1 = y1 * fmaxf(logsigf_(z1), -100.0f)
                         + (1.0f - y1) * fmaxf(logsigf_(-z1), -100.0f);
                acc += (double)t0 + (double)t1;
            }
        }
        if (tt == 0) out[0] = (float)(-acc / (double)(TT * 2));
        return;
    }

    // ================= LSTM layer blocks =================
    const int role = b >> 7;            // 0 = layer 1, 1 = layer 2
    const int j0   = (b & 127) * 4;     // 4 owned outputs
    const int p    = tt >> 3;           // row pair 0..15
    const int s    = tt & 7;            // 64-col slice
    const bool isB = (p >= 8);
    const int rr0  = 2 * (p & 7);       // 0,2,..,14 within 16-row gate set
    const int gate = rr0 >> 2;          // 4 rows per gate
    const int jj   = rr0 & 3;           // even: 0 or 2

    const float* WM = isB ? (role ? Whh1 : Whh0) : (role ? Wih1 : Wih0);
    const size_t ro = (size_t)(gate * HH + j0 + jj) * HH;

    ulonglong2 w0[16], w1[16];
#pragma unroll
    for (int i = 0; i < 16; i++) {
        int col = s * 64 + 4 * ((i + s) & 15);
        w0[i] = *(const ulonglong2*)(WM + ro + col);
        w1[i] = *(const ulonglong2*)(WM + ro + HH + col);
    }

    // bias folded into A-half s==0 accumulator init
    float biasLo0 = 0.f, biasLo1 = 0.f;
    if (!isB && s == 0) {
        const float* bi = role ? bih1 : bih0;
        const float* bh = role ? bhh1 : bhh0;
        biasLo0 = bi[gate * HH + j0 + jj]     + bh[gate * HH + j0 + jj];
        biasLo1 = bi[gate * HH + j0 + jj + 1] + bh[gate * HH + j0 + jj + 1];
    }

    float c = 0.f;
    if (tt < 4) c = c0[role * HH + j0 + tt];

    __shared__ float vecs[2 * HH];    // [A(512) | B(512)]
    __shared__ float gsum[4 * 12];    // transposed, stride 12: [jj][half4+gate]

    ull* myP = role ? g_p2 : g_p1;
    const int u = tt & 63;
    const ull* pA = g_p1 + HH + 8 * u;           // layer-2 A: h1 slot t+1 (threads<64)
    const ull* pB = myP + 8 * u;                 // own B: slot t (threads>=64)
    const float4* px = (const float4*)x + 2 * u; // layer-1 A (threads<64)
    ull* myOut = myP + HH + j0 + tt;             // producer store (tt<4)

    for (int t = 0; t < TT; t++, pA += HH, pB += HH, px += 128, myOut += HH) {
        // ---- poll + stage: each stager owns 8 floats = 4 mailbox pairs ----
        if (tt < 64) {
            if (role == 0) {
                float4 xa = __ldg(px);
                float4 xb = __ldg(px + 1);
                ((float4*)vecs)[2 * u]     = xa;
                ((float4*)vecs)[2 * u + 1] = xb;
            } else {
                const unsigned tgt = (unsigned)(t + 1);
                ulonglong2 v[4];
                uint pend = 0xFu;
                while (pend) {
                    ulonglong2 nv[4];
#pragma unroll
                    for (int i = 0; i < 4; i++)
                        if (pend & (1u << i)) nv[i] = ld_rlx2(pA + 2 * i);
#pragma unroll
                    for (int i = 0; i < 4; i++)
                        if (pend & (1u << i)) {
                            if ((hi_u(nv[i].x) == tgt) & (hi_u(nv[i].y) == tgt)) {
                                v[i] = nv[i];
                                pend &= ~(1u << i);
                            }
                        }
                }
                ((float4*)vecs)[2 * u] =
                    make_float4(lo_f(v[0].x), lo_f(v[0].y), lo_f(v[1].x), lo_f(v[1].y));
                ((float4*)vecs)[2 * u + 1] =
                    make_float4(lo_f(v[2].x), lo_f(v[2].y), lo_f(v[3].x), lo_f(v[3].y));
            }
        } else {
            const unsigned tgt = (unsigned)t;
            ulonglong2 v[4];
            uint pend = 0xFu;
            while (pend) {
                ulonglong2 nv[4];
#pragma unroll
                for (int i = 0; i < 4; i++)
                    if (pend & (1u << i)) nv[i] = ld_rlx2(pB + 2 * i);
#pragma unroll
                for (int i = 0; i < 4; i++)
                    if (pend & (1u << i)) {
                        if ((hi_u(nv[i].x) == tgt) & (hi_u(nv[i].y) == tgt)) {
                            v[i] = nv[i];
                            pend &= ~(1u << i);
                        }
                    }
            }
            ((float4*)(vecs + HH))[2 * u] =
                make_float4(lo_f(v[0].x), lo_f(v[0].y), lo_f(v[1].x), lo_f(v[1].y));
            ((float4*)(vecs + HH))[2 * u + 1] =
                make_float4(lo_f(v[2].x), lo_f(v[2].y), lo_f(v[3].x), lo_f(v[3].y));
        }
        __syncthreads();

        // ---- dual-row packed matvec over this thread's 64-col slice ----
        const float* vb = vecs + (isB ? HH : 0) + s * 64;
        ull a0 = packf2(biasLo0, 0.f);
        ull a1 = packf2(biasLo1, 0.f);
#pragma unroll
        for (int i = 0; i < 16; i++) {
            int idx = 4 * ((i + s) & 15);
            ulonglong2 v = *(const ulonglong2*)(vb + idx);
            ffma2(a0, w0[i].x, v.x);
            ffma2(a0, w0[i].y, v.y);
            ffma2(a1, w1[i].x, v.x);
            ffma2(a1, w1[i].y, v.y);
        }
        float2 f0 = unpack2(a0), f1 = unpack2(a1);
        float s0 = f0.x + f0.y, s1 = f1.x + f1.y;
        s0 += __shfl_xor_sync(0xffffffffu, s0, 1);
        s1 += __shfl_xor_sync(0xffffffffu, s1, 1);
        s0 += __shfl_xor_sync(0xffffffffu, s0, 2);
        s1 += __shfl_xor_sync(0xffffffffu, s1, 2);
        s0 += __shfl_xor_sync(0xffffffffu, s0, 4);
        s1 += __shfl_xor_sync(0xffffffffu, s1, 4);
        if (s == 0) {
            int half4 = isB ? 4 : 0;
            gsum[jj * 12 + half4 + gate]       = s0;   // row rr0
            gsum[(jj + 1) * 12 + half4 + gate] = s1;   // row rr0+1
        }
        __syncthreads();

        // ---- gates + cell update + publish ----
        if (tt < 4) {
            float4 qa = *(const float4*)(gsum + tt * 12);       // A: i,f,g,o (biased)
            float4 qb = *(const float4*)(gsum + tt * 12 + 4);   // B: i,f,g,o
            float ig = sig_fast(qa.x + qb.x);
            float fg = sig_fast(qa.y + qb.y);
            float gg = tanh_fast(qa.z + qb.z);
            float og = sig_fast(qa.w + qb.w);
            c = fg * c + ig * gg;
            float h = og * tanh_fast(c);
            st_rlx(myOut, packhf((unsigned)(t + 1), h));
        }
    }
}

extern "C" void kernel_launch(void* const* d_in, const int* in_sizes, int n_in,
                              void* d_out, int out_size) {
    const float* x     = (const float*)d_in[0];
    const float* truth = (const float*)d_in[1];
    const float* h0    = (const float*)d_in[2];
    const float* c0    = (const float*)d_in[3];
    const float* Wih0  = (const float*)d_in[4];
    const float* Whh0  = (const float*)d_in[5];
    const float* bih0  = (const float*)d_in[6];
    const float* bhh0  = (const float*)d_in[7];
    const float* Wih1  = (const float*)d_in[8];
    const float* Whh1  = (const float*)d_in[9];
    const float* bih1  = (const float*)d_in[10];
    const float* bhh1  = (const float*)d_in[11];
    const float* Whead = (const float*)d_in[12];
    const float* bhead = (const float*)d_in[13];
    float* out = (float*)d_out;

    clear_kernel<<<256, 1024>>>(h0);
    lstm_kernel<<<257, 128>>>(x, truth, c0,
                              Wih0, Whh0, bih0, bhh0,
                              Wih1, Whh1, bih1, bhh1,
                              Whead, bhead, out);
}

// round 12
// speedup vs baseline: 2.0091x; 2.0091x over previous
#include <cuda_runtime.h>
#include <math.h>

typedef unsigned long long ull;
typedef unsigned int uint;

#define TT 8192
#define HH 512

// ---------------- scratch: packed {flag(hi32), h_bits(lo32)} mailboxes ----------------
__device__ __align__(256) ull g_p1[(TT + 1) * HH];
__device__ __align__(256) ull g_p2[(TT + 1) * HH];

// ---------------- primitives ----------------
__device__ __forceinline__ ulonglong2 ld_rlx2(const ull* p) {
    ulonglong2 v;
    asm volatile("ld.relaxed.gpu.global.v2.u64 {%0,%1}, [%2];"
                 : "=l"(v.x), "=l"(v.y) : "l"(p) : "memory");
    return v;
}
__device__ __forceinline__ void st_rlx(ull* p, ull v) {
    asm volatile("st.relaxed.gpu.global.u64 [%0], %1;" :: "l"(p), "l"(v) : "memory");
}
__device__ __forceinline__ ull packhf(unsigned flag, float h) {
    return ((ull)flag << 32) | (ull)__float_as_uint(h);
}
__device__ __forceinline__ float lo_f(ull v) { return __uint_as_float((unsigned)v); }
__device__ __forceinline__ unsigned hi_u(ull v) { return (unsigned)(v >> 32); }

// spin until this v2 mailbox pair carries flag==tgt, return the two payloads
__device__ __forceinline__ float2 pollv2(const ull* p, unsigned tgt) {
    ulonglong2 v;
    for (;;) {
        v = ld_rlx2(p);
        if ((hi_u(v.x) == tgt) & (hi_u(v.y) == tgt)) break;
    }
    return make_float2(lo_f(v.x), lo_f(v.y));
}

__device__ __forceinline__ void ffma2(ull& acc, ull w, ull v) {
    asm("fma.rn.f32x2 %0, %1, %2, %0;" : "+l"(acc) : "l"(w), "l"(v));
}
__device__ __forceinline__ ull packf2(float a, float b) {
    ull r;
    asm("mov.b64 %0, {%1,%2};" : "=l"(r) : "f"(a), "f"(b));
    return r;
}
__device__ __forceinline__ float2 unpack2(ull v) {
    float a, b;
    asm("mov.b64 {%0,%1}, %2;" : "=f"(a), "=f"(b) : "l"(v));
    return make_float2(a, b);
}
__device__ __forceinline__ float tanh_fast(float x) {
    float r;
    asm("tanh.approx.f32 %0, %1;" : "=f"(r) : "f"(x));
    return r;
}
__device__ __forceinline__ float sig_fast(float x) {
    return fmaf(tanh_fast(0.5f * x), 0.5f, 0.5f);
}
__device__ __forceinline__ float logsigf_(float z) {
    if (z >= 0.0f) return -log1pf(expf(-z));
    return z - log1pf(expf(z));
}

// ---------------- clear + seed ----------------
__global__ void clear_kernel(const float* __restrict__ h0) {
    size_t i = (size_t)blockIdx.x * blockDim.x + threadIdx.x;
    if (i < HH) {
        g_p1[i] = packhf(0u, h0[i]);
        g_p2[i] = packhf(0u, h0[HH + i]);
    }
    const size_t N2 = (size_t)TT * HH / 2;
    ulonglong2* a = (ulonglong2*)(g_p1 + HH);
    ulonglong2* b = (ulonglong2*)(g_p2 + HH);
    ulonglong2 z; z.x = 0ull; z.y = 0ull;
    size_t stride = (size_t)gridDim.x * blockDim.x;
    for (size_t k = i; k < N2; k += stride) { a[k] = z; b[k] = z; }
}

// ---------------- persistent pipelined LSTM ----------------
// 129 blocks x 256 threads — R10 structure. Changes:
//   * split staging: threads [0,128) own vec A (float4 each), [128,256) own vec B;
//     each spins on ONE scout v2, then verifies the partner v2 (halves spin streams)
//   * producers (gate threads) moved to warp 7 (hi-wid arbiter priority after bar2)
__global__ void __launch_bounds__(256, 1) lstm_kernel(
    const float* __restrict__ x,
    const float* __restrict__ truth,
    const float* __restrict__ c0,
    const float* __restrict__ Wih0, const float* __restrict__ Whh0,
    const float* __restrict__ bih0, const float* __restrict__ bhh0,
    const float* __restrict__ Wih1, const float* __restrict__ Whh1,
    const float* __restrict__ bih1, const float* __restrict__ bhh1,
    const float* __restrict__ Whead, const float* __restrict__ bhead,
    float* __restrict__ out)
{
    const int b  = blockIdx.x;
    const int tt = threadIdx.x;

    // ================= HEAD + LOSS =================
    if (b == 128) {
        if (tt >= 32) return;
        float w0[16], w1[16];
#pragma unroll
        for (int i = 0; i < 16; i++) {
            w0[i] = Whead[tt * 16 + i];
            w1[i] = Whead[HH + tt * 16 + i];
        }
        const float bb0 = bhead[0], bb1 = bhead[1];
        double acc = 0.0;
        const ull* pe = g_p2 + HH + tt * 16;
        for (int t = 0; t < TT; t++, pe += HH) {
            const unsigned tgt = (unsigned)(t + 1);
            ulonglong2 v[8];
            uint pend = 0xFFu;
            while (pend) {
                ulonglong2 nv[8];
#pragma unroll
                for (int i = 0; i < 8; i++)
                    if (pend & (1u << i)) nv[i] = ld_rlx2(pe + 2 * i);
#pragma unroll
                for (int i = 0; i < 8; i++)
                    if (pend & (1u << i)) {
                        if ((hi_u(nv[i].x) == tgt) & (hi_u(nv[i].y) == tgt)) {
                            v[i] = nv[i];
                            pend &= ~(1u << i);
                        }
                    }
            }
            float s0 = 0.f, s1 = 0.f;
#pragma unroll
            for (int i = 0; i < 8; i++) {
                float h0v = lo_f(v[i].x), h1v = lo_f(v[i].y);
                s0 = fmaf(w0[2 * i], h0v, s0);
                s1 = fmaf(w1[2 * i], h0v, s1);
                s0 = fmaf(w0[2 * i + 1], h1v, s0);
                s1 = fmaf(w1[2 * i + 1], h1v, s1);
            }
#pragma unroll
            for (int m = 16; m >= 1; m >>= 1) {
                s0 += __shfl_xor_sync(0xffffffffu, s0, m);
                s1 += __shfl_xor_sync(0xffffffffu, s1, m);
            }
            if (tt == 0) {
                float z0 = s0 + bb0, z1 = s1 + bb1;
                float y0 = __ldg(truth + t * 2 + 0), y1 = __ldg(truth + t * 2 + 1);
                float t0 = y0 * fmaxf(logsigf_(z0), -100.0f)
                         + (1.0f - y0) * fmaxf(logsigf_(-z0), -100.0f);
                float t1 = y1 * fmaxf(logsigf_(z1), -100.0f)
                         + (1.0f - y1) * fmaxf(logsigf_(-z1), -100.0f);
                acc += (double)t0 + (double)t1;
            }
        }
        if (tt == 0) out[0] = (float)(-acc / (double)(TT * 2));
        return;
    }

    // ================= LSTM layer blocks =================
    const int role = b >> 6;
    const int j0   = (b & 63) * 8;
    const int p    = tt >> 3;           // row pair 0..31
    const int s    = tt & 7;            // 64-col slice
    const bool isB = (p >= 16);
    const int rr0  = 2 * (p & 15);
    const int gate = rr0 >> 3;
    const int jj   = rr0 & 7;

    const float* WM = isB ? (role ? Whh1 : Whh0) : (role ? Wih1 : Wih0);
    const size_t ro = (size_t)(gate * HH + j0 + jj) * HH;

    ulonglong2 w0[16], w1[16];
#pragma unroll
    for (int i = 0; i < 16; i++) {
        int col = s * 64 + 4 * ((i + s) & 15);
        w0[i] = *(const ulonglong2*)(WM + ro + col);
        w1[i] = *(const ulonglong2*)(WM + ro + HH + col);
    }

    // bias folded into A-half s==0 accumulator init
    float biasLo0 = 0.f, biasLo1 = 0.f;
    if (!isB && s == 0) {
        const float* bi = role ? bih1 : bih0;
        const float* bh = role ? bhh1 : bhh0;
        biasLo0 = bi[gate * HH + j0 + jj]     + bh[gate * HH + j0 + jj];
        biasLo1 = bi[gate * HH + j0 + jj + 1] + bh[gate * HH + j0 + jj + 1];
    }

    // producers live in warp 7 (tt 248..255): highest arbiter priority after bar2
    const bool isProd = (tt >= 248);
    const int  jp     = tt - 248;       // producer's output index 0..7
    float c = 0.f;
    if (isProd) c = c0[role * HH + j0 + jp];

    __shared__ float vecs[2 * HH];   // [A(512) | B(512)]
    __shared__ float gsum[64];       // transposed: [jj][half*4 + gate]

    ull* myP = role ? g_p2 : g_p1;
    const int u = tt & 127;
    // A stagers (tt<128): elements 4u..4u+3 of layer input
    const ull* pA = g_p1 + HH + 4 * u;           // layer-2: h1 slot t+1
    const float4* px = (const float4*)x + u;     // layer-1: x row t
    // B stagers (tt>=128): elements 4u..4u+3 of own h slot t
    const ull* pB = myP + 4 * u;
    ull* myOut = myP + HH + j0 + jp;             // producer store (warp 7)

    for (int t = 0; t < TT; t++, pA += HH, pB += HH, px += 128, myOut += HH) {
        // ---- scout-then-partner poll + stage ----
        if (tt < 128) {
            float4 va;
            if (role == 0) {
                va = __ldg(px);
            } else {
                const unsigned tgt = (unsigned)(t + 1);
                float2 sc = pollv2(pA, tgt);        // scout spin
                float2 pr = pollv2(pA + 2, tgt);    // partner verify (≈1 iter)
                va = make_float4(sc.x, sc.y, pr.x, pr.y);
            }
            ((float4*)vecs)[u] = va;
        } else {
            const unsigned tgt = (unsigned)t;
            float2 sc = pollv2(pB, tgt);            // scout spin
            float2 pr = pollv2(pB + 2, tgt);        // partner verify (≈1 iter)
            ((float4*)(vecs + HH))[u] = make_float4(sc.x, sc.y, pr.x, pr.y);
        }
        __syncthreads();

        // ---- dual-row packed matvec over this thread's 64-col slice ----
        const float* vb = vecs + (isB ? HH : 0) + s * 64;
        ull a0 = packf2(biasLo0, 0.f);
        ull a1 = packf2(biasLo1, 0.f);
#pragma unroll
        for (int i = 0; i < 16; i++) {
            int idx = 4 * ((i + s) & 15);
            ulonglong2 v = *(const ulonglong2*)(vb + idx);
            ffma2(a0, w0[i].x, v.x);
            ffma2(a0, w0[i].y, v.y);
            ffma2(a1, w1[i].x, v.x);
            ffma2(a1, w1[i].y, v.y);
        }
        float2 f0 = unpack2(a0), f1 = unpack2(a1);
        float s0 = f0.x + f0.y, s1 = f1.x + f1.y;
        s0 += __shfl_xor_sync(0xffffffffu, s0, 1);
        s1 += __shfl_xor_sync(0xffffffffu, s1, 1);
        s0 += __shfl_xor_sync(0xffffffffu, s0, 2);
        s1 += __shfl_xor_sync(0xffffffffu, s1, 2);
        s0 += __shfl_xor_sync(0xffffffffu, s0, 4);
        s1 += __shfl_xor_sync(0xffffffffu, s1, 4);
        if (s == 0) {
            int half4 = isB ? 4 : 0;
            gsum[jj * 8 + half4 + gate]       = s0;   // row rr0
            gsum[(jj + 1) * 8 + half4 + gate] = s1;   // row rr0+1
        }
        __syncthreads();

        // ---- gates + cell update + publish (warp 7) ----
        if (isProd) {
            float4 qa = *(const float4*)(gsum + jp * 8);       // A: i,f,g,o (biased)
            float4 qb = *(const float4*)(gsum + jp * 8 + 4);   // B: i,f,g,o
            float ig = sig_fast(qa.x + qb.x);
            float fg = sig_fast(qa.y + qb.y);
            float gg = tanh_fast(qa.z + qb.z);
            float og = sig_fast(qa.w + qb.w);
            c = fg * c + ig * gg;
            float h = og * tanh_fast(c);
            st_rlx(myOut, packhf((unsigned)(t + 1), h));
        }
    }
}

extern "C" void kernel_launch(void* const* d_in, const int* in_sizes, int n_in,
                              void* d_out, int out_size) {
    const float* x     = (const float*)d_in[0];
    const float* truth = (const float*)d_in[1];
    const float* h0    = (const float*)d_in[2];
    const float* c0    = (const float*)d_in[3];
    const float* Wih0  = (const float*)d_in[4];
    const float* Whh0  = (const float*)d_in[5];
    const float* bih0  = (const float*)d_in[6];
    const float* bhh0  = (const float*)d_in[7];
    const float* Wih1  = (const float*)d_in[8];
    const float* Whh1  = (const float*)d_in[9];
    const float* bih1  = (const float*)d_in[10];
    const float* bhh1  = (const float*)d_in[11];
    const float* Whead = (const float*)d_in[12];
    const float* bhead = (const float*)d_in[13];
    float* out = (float*)d_out;

    clear_kernel<<<256, 1024>>>(h0);
    lstm_kernel<<<129, 256>>>(x, truth, c0,
                              Wih0, Whh0, bih0, bhh0,
                              Wih1, Whh1, bih1, bhh1,
                              Whead, bhead, out);
}